// round 1
// baseline (speedup 1.0000x reference)
#include <cuda_runtime.h>
#include <cuda_bf16.h>

#define NN 100000
#define NE 1600000
#define HD 128
#define VC 1000
#define NB_SCAN 98   // ceil(100000/1024)

// ---------------- scratch (device globals; no allocation allowed) ----------
__device__ float g_hA[NN * HD];
__device__ float g_hB[NN * HD];
__device__ float g_mean[NN * HD];
__device__ int   g_cnt[NN];
__device__ int   g_off[NN + 1];
__device__ int   g_cur[NN];
__device__ int   g_srcs[NE];
__device__ int   g_bsum[NB_SCAN];

// ---------------- CSR build -------------------------------------------------
__global__ void k_zero() {
    int i = blockIdx.x * blockDim.x + threadIdx.x;
    if (i < NN) { g_cnt[i] = 0; g_cur[i] = 0; }
}

__global__ void k_hist(const int* __restrict__ dst) {
    int e = blockIdx.x * blockDim.x + threadIdx.x;
    if (e < NE) atomicAdd(&g_cnt[dst[e]], 1);
}

__global__ void k_scan1() {  // inclusive scan within 1024-blocks -> g_off, block totals -> g_bsum
    __shared__ int s[1024];
    int i = blockIdx.x * 1024 + threadIdx.x;
    int v = (i < NN) ? g_cnt[i] : 0;
    s[threadIdx.x] = v;
    __syncthreads();
    for (int o = 1; o < 1024; o <<= 1) {
        int t = (threadIdx.x >= o) ? s[threadIdx.x - o] : 0;
        __syncthreads();
        s[threadIdx.x] += t;
        __syncthreads();
    }
    if (i < NN) g_off[i] = s[threadIdx.x];
    if (threadIdx.x == 1023) g_bsum[blockIdx.x] = s[1023];
}

__global__ void k_scan2() {  // serial exclusive scan of 98 block sums
    if (threadIdx.x == 0 && blockIdx.x == 0) {
        int acc = 0;
        for (int b = 0; b < NB_SCAN; b++) { int t = g_bsum[b]; g_bsum[b] = acc; acc += t; }
    }
}

__global__ void k_scan3() {  // convert to exclusive offsets
    int i = blockIdx.x * 1024 + threadIdx.x;
    if (i < NN) g_off[i] = g_off[i] - g_cnt[i] + g_bsum[blockIdx.x];
    if (i == 0) g_off[NN] = NE;
}

__global__ void k_scatter(const int* __restrict__ src, const int* __restrict__ dst) {
    int e = blockIdx.x * blockDim.x + threadIdx.x;
    if (e < NE) {
        int d = dst[e];
        int p = g_off[d] + atomicAdd(&g_cur[d], 1);
        g_srcs[p] = src[e];
    }
}

// ---------------- embedding gather ------------------------------------------
__global__ void k_embed(const int* __restrict__ x, const float* __restrict__ emb) {
    int i = blockIdx.x * blockDim.x + threadIdx.x;  // NN*32 threads, float4 each
    if (i < NN * 32) {
        int n = i >> 5, c = i & 31;
        ((float4*)g_hA)[i] = ((const float4*)emb)[x[n] * 32 + c];
    }
}

// ---------------- mean aggregation: one warp per node ------------------------
__global__ void k_agg(const float* __restrict__ h) {
    int w = (blockIdx.x * blockDim.x + threadIdx.x) >> 5;
    int lane = threadIdx.x & 31;
    if (w >= NN) return;
    int beg = g_off[w], end = g_off[w + 1];
    float4 acc = make_float4(0.f, 0.f, 0.f, 0.f);
    const float4* h4 = (const float4*)h;
    for (int i = beg; i < end; i++) {
        int s = g_srcs[i];
        float4 v = h4[s * 32 + lane];
        acc.x += v.x; acc.y += v.y; acc.z += v.z; acc.w += v.w;
    }
    float inv = 1.0f / fmaxf((float)(end - beg), 1.0f);
    acc.x *= inv; acc.y *= inv; acc.z *= inv; acc.w *= inv;
    ((float4*)g_mean)[w * 32 + lane] = acc;
}

// ---------------- per-layer fused GEMM: relu([mean|h] @ [Wl;Wr] + b) ----------
// BM=64, BN=128, BK=32, 256 threads, TM=8 x TN=4 per thread
__global__ void k_gemm_layer(const float* __restrict__ hin, float* __restrict__ hout,
                             const float* __restrict__ Wl, const float* __restrict__ Wr,
                             const float* __restrict__ b) {
    __shared__ float As[64][32];
    __shared__ float Bs[32][128];
    int row0 = blockIdx.x * 64;
    int tid = threadIdx.x;
    int ty = tid >> 5, tx = tid & 31;   // ty 0..7 (rows), tx 0..31 (cols)
    float acc[8][4] = {};
    for (int k0 = 0; k0 < 256; k0 += 32) {
        // load A (64 x 32): coalesced along k, conflict-free store
        #pragma unroll
        for (int idx = tid; idx < 64 * 32; idx += 256) {
            int nl = idx >> 5, kk = idx & 31;
            int n = row0 + nl, k = k0 + kk;
            float v = 0.f;
            if (n < NN) v = (k < HD) ? g_mean[n * HD + k] : hin[n * HD + (k - HD)];
            As[nl][kk] = v;
        }
        // load B (32 x 128)
        #pragma unroll
        for (int idx = tid; idx < 32 * 128; idx += 256) {
            int kk = idx >> 7, j = idx & 127;
            int k = k0 + kk;
            Bs[kk][j] = (k < HD) ? Wl[k * HD + j] : Wr[(k - HD) * HD + j];
        }
        __syncthreads();
        #pragma unroll
        for (int kk = 0; kk < 32; kk++) {
            float4 bv = *(const float4*)&Bs[kk][tx * 4];
            #pragma unroll
            for (int i = 0; i < 8; i++) {
                float a = As[ty * 8 + i][kk];
                acc[i][0] += a * bv.x;
                acc[i][1] += a * bv.y;
                acc[i][2] += a * bv.z;
                acc[i][3] += a * bv.w;
            }
        }
        __syncthreads();
    }
    float4 bb = *(const float4*)&b[tx * 4];
    #pragma unroll
    for (int i = 0; i < 8; i++) {
        int n = row0 + ty * 8 + i;
        if (n < NN) {
            float4 o;
            o.x = fmaxf(acc[i][0] + bb.x, 0.f);
            o.y = fmaxf(acc[i][1] + bb.y, 0.f);
            o.z = fmaxf(acc[i][2] + bb.z, 0.f);
            o.w = fmaxf(acc[i][3] + bb.w, 0.f);
            ((float4*)hout)[n * 32 + tx] = o;
        }
    }
}

// ---------------- final GEMM: logits = h @ Wlast + blast ---------------------
// BM=128, BN=128, BK=32, 256 threads, TM=8 x TN=8
__global__ void k_gemm_last(const float* __restrict__ hin, const float* __restrict__ W,
                            const float* __restrict__ b, float* __restrict__ out) {
    __shared__ float As[128][32];
    __shared__ float Bs[32][128];
    int row0 = blockIdx.x * 128;
    int col0 = blockIdx.y * 128;
    int tid = threadIdx.x;
    int ty = tid >> 4, tx = tid & 15;   // ty 0..15 rows, tx 0..15 cols
    float acc[8][8] = {};
    for (int k0 = 0; k0 < HD; k0 += 32) {
        #pragma unroll
        for (int idx = tid; idx < 128 * 32; idx += 256) {
            int nl = idx >> 5, kk = idx & 31;
            int n = row0 + nl;
            As[nl][kk] = (n < NN) ? hin[n * HD + k0 + kk] : 0.f;
        }
        #pragma unroll
        for (int idx = tid; idx < 32 * 128; idx += 256) {
            int kk = idx >> 7, j = idx & 127;
            int c = col0 + j;
            Bs[kk][j] = (c < VC) ? W[(k0 + kk) * VC + c] : 0.f;
        }
        __syncthreads();
        #pragma unroll
        for (int kk = 0; kk < 32; kk++) {
            float av[8];
            #pragma unroll
            for (int i = 0; i < 8; i++) av[i] = As[ty * 8 + i][kk];
            float4 b0 = *(const float4*)&Bs[kk][tx * 8];
            float4 b1 = *(const float4*)&Bs[kk][tx * 8 + 4];
            float bv[8] = {b0.x, b0.y, b0.z, b0.w, b1.x, b1.y, b1.z, b1.w};
            #pragma unroll
            for (int i = 0; i < 8; i++)
                #pragma unroll
                for (int j = 0; j < 8; j++)
                    acc[i][j] += av[i] * bv[j];
        }
        __syncthreads();
    }
    #pragma unroll
    for (int i = 0; i < 8; i++) {
        int n = row0 + ty * 8 + i;
        if (n >= NN) continue;
        #pragma unroll
        for (int j = 0; j < 8; j++) {
            int c = col0 + tx * 8 + j;
            if (c < VC) out[(long)n * VC + c] = acc[i][j] + b[c];
        }
    }
}

// ---------------- softmax over 1000 classes, one warp per node ----------------
__global__ void k_softmax(float* __restrict__ out) {
    int w = (blockIdx.x * blockDim.x + threadIdx.x) >> 5;
    int lane = threadIdx.x & 31;
    if (w >= NN) return;
    float* row = out + (long)w * VC;
    float vals[32];
    float m = -1e30f;
    #pragma unroll
    for (int i = 0; i < 32; i++) {
        int c = lane + i * 32;
        float v = (c < VC) ? row[c] : -1e30f;
        vals[i] = v;
        m = fmaxf(m, v);
    }
    #pragma unroll
    for (int o = 16; o; o >>= 1) m = fmaxf(m, __shfl_xor_sync(0xffffffffu, m, o));
    float s = 0.f;
    #pragma unroll
    for (int i = 0; i < 32; i++) {
        float e = __expf(vals[i] - m);
        vals[i] = e;
        s += e;
    }
    #pragma unroll
    for (int o = 16; o; o >>= 1) s += __shfl_xor_sync(0xffffffffu, s, o);
    float inv = 1.0f / s;
    #pragma unroll
    for (int i = 0; i < 32; i++) {
        int c = lane + i * 32;
        if (c < VC) row[c] = vals[i] * inv;
    }
}

// ---------------- launch ------------------------------------------------------
extern "C" void kernel_launch(void* const* d_in, const int* in_sizes, int n_in,
                              void* d_out, int out_size) {
    const int*   x     = (const int*)d_in[0];
    const int*   ei    = (const int*)d_in[1];
    const int*   src   = ei;
    const int*   dst   = ei + NE;
    const float* emb   = (const float*)d_in[2];
    const float* Wl    = (const float*)d_in[3];
    const float* bl    = (const float*)d_in[4];
    const float* Wr    = (const float*)d_in[5];
    const float* Wlast = (const float*)d_in[6];
    const float* blast = (const float*)d_in[7];
    float* out = (float*)d_out;

    float *hA, *hB;
    cudaGetSymbolAddress((void**)&hA, g_hA);
    cudaGetSymbolAddress((void**)&hB, g_hB);

    k_zero<<<(NN + 255) / 256, 256>>>();
    k_hist<<<(NE + 255) / 256, 256>>>(dst);
    k_scan1<<<NB_SCAN, 1024>>>();
    k_scan2<<<1, 32>>>();
    k_scan3<<<NB_SCAN, 1024>>>();
    k_scatter<<<(NE + 255) / 256, 256>>>(src, dst);
    k_embed<<<(NN * 32 + 255) / 256, 256>>>(x, emb);

    float* hin = hA;
    float* hout = hB;
    for (int l = 0; l < 3; l++) {
        k_agg<<<(NN * 32 + 255) / 256, 256>>>(hin);
        k_gemm_layer<<<(NN + 63) / 64, 256>>>(hin, hout,
                                              Wl + l * HD * HD, Wr + l * HD * HD,
                                              bl + l * HD);
        float* t = hin; hin = hout; hout = t;
    }

    dim3 g((NN + 127) / 128, (VC + 127) / 128);
    k_gemm_last<<<g, 256>>>(hin, Wlast, blast, out);
    k_softmax<<<(NN * 32 + 255) / 256, 256>>>(out);
}

// round 3
// speedup vs baseline: 2.5908x; 2.5908x over previous
#include <cuda_runtime.h>
#include <cuda_bf16.h>
#include <cstdint>

#define NN 100000
#define NE 1600000
#define HD 128
#define VC 1000
#define NB_SCAN 98          // ceil(100000/1024)
#define NT 782              // ceil(100000/128) M-tiles
#define MROWS (NT * 128)    // 100096 padded rows

// ---------------- scratch (device globals; no allocation allowed) ----------
__device__ float g_hA[NN * HD];
__device__ float g_hB[NN * HD];
__device__ float g_mean[NN * HD];
__device__ int   g_cnt[NN];
__device__ int   g_off[NN + 1];
__device__ int   g_cur[NN];
__device__ int   g_srcs[NE];
__device__ int   g_bsum[NB_SCAN];

// bf16-split operand buffers (plain row-major, K-major)
__device__ __nv_bfloat16 g_Ahi[MROWS * 256];    // layer A = [mean|h], K=256
__device__ __nv_bfloat16 g_Alo[MROWS * 256];
__device__ __nv_bfloat16 g_FAhi[MROWS * 128];   // final A = h, K=128
__device__ __nv_bfloat16 g_FAlo[MROWS * 128];
__device__ __nv_bfloat16 g_BthiL[128 * 256];    // layer Bt[n][k] = [Wl;Wr][k][n]
__device__ __nv_bfloat16 g_BtloL[128 * 256];
__device__ __nv_bfloat16 g_BthiF[1024 * 128];   // final Bt[n][k] = Wlast[k][n]
__device__ __nv_bfloat16 g_BtloF[1024 * 128];

// ---------------- CSR build -------------------------------------------------
__global__ void k_zero() {
    int i = blockIdx.x * blockDim.x + threadIdx.x;
    if (i < NN) { g_cnt[i] = 0; g_cur[i] = 0; }
}
__global__ void k_hist(const int* __restrict__ dst) {
    int e = blockIdx.x * blockDim.x + threadIdx.x;
    if (e < NE) atomicAdd(&g_cnt[dst[e]], 1);
}
__global__ void k_scan1() {
    __shared__ int s[1024];
    int i = blockIdx.x * 1024 + threadIdx.x;
    int v = (i < NN) ? g_cnt[i] : 0;
    s[threadIdx.x] = v;
    __syncthreads();
    for (int o = 1; o < 1024; o <<= 1) {
        int t = (threadIdx.x >= o) ? s[threadIdx.x - o] : 0;
        __syncthreads();
        s[threadIdx.x] += t;
        __syncthreads();
    }
    if (i < NN) g_off[i] = s[threadIdx.x];
    if (threadIdx.x == 1023) g_bsum[blockIdx.x] = s[1023];
}
__global__ void k_scan2() {
    if (threadIdx.x == 0 && blockIdx.x == 0) {
        int acc = 0;
        for (int b = 0; b < NB_SCAN; b++) { int t = g_bsum[b]; g_bsum[b] = acc; acc += t; }
    }
}
__global__ void k_scan3() {
    int i = blockIdx.x * 1024 + threadIdx.x;
    if (i < NN) g_off[i] = g_off[i] - g_cnt[i] + g_bsum[blockIdx.x];
    if (i == 0) g_off[NN] = NE;
}
__global__ void k_scatter(const int* __restrict__ src, const int* __restrict__ dst) {
    int e = blockIdx.x * blockDim.x + threadIdx.x;
    if (e < NE) {
        int d = dst[e];
        int p = g_off[d] + atomicAdd(&g_cur[d], 1);
        g_srcs[p] = src[e];
    }
}

// ---------------- embedding gather ------------------------------------------
__global__ void k_embed(const int* __restrict__ x, const float* __restrict__ emb) {
    int i = blockIdx.x * blockDim.x + threadIdx.x;
    if (i < NN * 32) {
        int n = i >> 5, c = i & 31;
        ((float4*)g_hA)[i] = ((const float4*)emb)[x[n] * 32 + c];
    }
}

// ---------------- mean aggregation: one warp per node ------------------------
__global__ void k_agg(const float* __restrict__ h) {
    int w = (blockIdx.x * blockDim.x + threadIdx.x) >> 5;
    int lane = threadIdx.x & 31;
    if (w >= NN) return;
    int beg = g_off[w], end = g_off[w + 1];
    float4 acc = make_float4(0.f, 0.f, 0.f, 0.f);
    const float4* h4 = (const float4*)h;
    for (int i = beg; i < end; i++) {
        int s = g_srcs[i];
        float4 v = h4[s * 32 + lane];
        acc.x += v.x; acc.y += v.y; acc.z += v.z; acc.w += v.w;
    }
    float inv = 1.0f / fmaxf((float)(end - beg), 1.0f);
    acc.x *= inv; acc.y *= inv; acc.z *= inv; acc.w *= inv;
    ((float4*)g_mean)[w * 32 + lane] = acc;
}

// ---------------- bf16 hi/lo split helpers ------------------------------------
__device__ __forceinline__ void split2(float v0, float v1, uint32_t& hi, uint32_t& lo) {
    __nv_bfloat16 h0 = __float2bfloat16(v0);
    __nv_bfloat16 h1 = __float2bfloat16(v1);
    __nv_bfloat16 l0 = __float2bfloat16(v0 - __bfloat162float(h0));
    __nv_bfloat16 l1 = __float2bfloat16(v1 - __bfloat162float(h1));
    __nv_bfloat162 hp = __nv_bfloat162(h0, h1);
    __nv_bfloat162 lp = __nv_bfloat162(l0, l1);
    hi = *(uint32_t*)&hp;
    lo = *(uint32_t*)&lp;
}

// layer A: [mean | h], row stride 256
__global__ void k_convA_L(const float* __restrict__ h) {
    int idx = blockIdx.x * blockDim.x + threadIdx.x;   // MROWS*128 threads, 2 elems each
    if (idx >= MROWS * 128) return;
    int row = idx >> 7, kp = idx & 127;
    float v0 = 0.f, v1 = 0.f;
    if (row < NN) {
        const float* srcp = (kp < 64) ? &g_mean[row * HD + kp * 2]
                                      : &h[row * HD + (kp - 64) * 2];
        float2 v = *(const float2*)srcp;
        v0 = v.x; v1 = v.y;
    }
    uint32_t hi, lo;
    split2(v0, v1, hi, lo);
    ((uint32_t*)g_Ahi)[row * 128 + kp] = hi;
    ((uint32_t*)g_Alo)[row * 128 + kp] = lo;
}

// final A: h, row stride 128
__global__ void k_convA_F(const float* __restrict__ h) {
    int idx = blockIdx.x * blockDim.x + threadIdx.x;   // MROWS*64 threads
    if (idx >= MROWS * 64) return;
    int row = idx >> 6, kp = idx & 63;
    float v0 = 0.f, v1 = 0.f;
    if (row < NN) {
        float2 v = *(const float2*)&h[row * HD + kp * 2];
        v0 = v.x; v1 = v.y;
    }
    uint32_t hi, lo;
    split2(v0, v1, hi, lo);
    ((uint32_t*)g_FAhi)[row * 64 + kp] = hi;
    ((uint32_t*)g_FAlo)[row * 64 + kp] = lo;
}

// layer B: Bt[n][k], k<128 -> Wl[k][n], else Wr[k-128][n]
__global__ void k_convB_L(const float* __restrict__ Wl, const float* __restrict__ Wr) {
    int idx = blockIdx.x * blockDim.x + threadIdx.x;   // 128*128 threads, 2 k each
    if (idx >= 128 * 128) return;
    int n = idx >> 7, kp = idx & 127;
    int k = kp * 2;
    float v0 = (k < HD) ? Wl[k * HD + n] : Wr[(k - HD) * HD + n];
    float v1 = (k + 1 < HD) ? Wl[(k + 1) * HD + n] : Wr[(k + 1 - HD) * HD + n];
    uint32_t hi, lo;
    split2(v0, v1, hi, lo);
    ((uint32_t*)g_BthiL)[n * 128 + kp] = hi;
    ((uint32_t*)g_BtloL)[n * 128 + kp] = lo;
}

// final B: Bt[n][k] = Wlast[k][n], n padded to 1024
__global__ void k_convB_F(const float* __restrict__ W) {
    int idx = blockIdx.x * blockDim.x + threadIdx.x;   // 1024*64 threads
    if (idx >= 1024 * 64) return;
    int n = idx >> 6, kp = idx & 63;
    int k = kp * 2;
    float v0 = 0.f, v1 = 0.f;
    if (n < VC) {
        v0 = W[k * VC + n];
        v1 = W[(k + 1) * VC + n];
    }
    uint32_t hi, lo;
    split2(v0, v1, hi, lo);
    ((uint32_t*)g_BthiF)[n * 64 + kp] = hi;
    ((uint32_t*)g_BtloF)[n * 64 + kp] = lo;
}

// ---------------- mma.sync GEMM ------------------------------------------------
// CTA tile 128x128, 8 warps (4M x 2N), warp tile 32x64, K-chunk 64.
// 3-pass bf16 split: hi*hi + hi*lo + lo*hi, fp32 accumulate.
#define MMA4(c, a, b0, b1) \
    asm volatile("mma.sync.aligned.m16n8k16.row.col.f32.bf16.bf16.f32 " \
        "{%0,%1,%2,%3}, {%4,%5,%6,%7}, {%8,%9}, {%0,%1,%2,%3};" \
        : "+f"((c)[0]), "+f"((c)[1]), "+f"((c)[2]), "+f"((c)[3]) \
        : "r"((a)[0]), "r"((a)[1]), "r"((a)[2]), "r"((a)[3]), "r"(b0), "r"(b1))

#define GSMEM 73728   // 4 buffers x 128 rows x 72 bf16 (144B padded rows)

template<int KTOT, bool RELU>
__global__ void __launch_bounds__(256) k_mma_gemm(
    const __nv_bfloat16* __restrict__ Ahi, const __nv_bfloat16* __restrict__ Alo,
    const __nv_bfloat16* __restrict__ Bthi, const __nv_bfloat16* __restrict__ Btlo,
    const float* __restrict__ bias, float* __restrict__ out,
    int outStride, int ncols)
{
    extern __shared__ __align__(16) char smem[];
    __nv_bfloat16* sAhi = (__nv_bfloat16*)(smem);
    __nv_bfloat16* sAlo = (__nv_bfloat16*)(smem + 18432);
    __nv_bfloat16* sBhi = (__nv_bfloat16*)(smem + 36864);
    __nv_bfloat16* sBlo = (__nv_bfloat16*)(smem + 55296);

    int tid = threadIdx.x;
    int lane = tid & 31, wid = tid >> 5;
    int wm = wid & 3, wn = wid >> 2;
    int mbase = blockIdx.x * 128;
    int nbase = blockIdx.y * 128;

    float acc[2][8][4];
    #pragma unroll
    for (int i = 0; i < 2; i++)
        #pragma unroll
        for (int j = 0; j < 8; j++)
            #pragma unroll
            for (int q = 0; q < 4; q++) acc[i][j][q] = 0.f;

    for (int kc = 0; kc < KTOT; kc += 64) {
        __syncthreads();
        #pragma unroll
        for (int i = tid; i < 2048; i += 256) {
            int r = i >> 4, kq = i & 15;
            size_t ga = (size_t)(mbase + r) * KTOT + kc + kq * 4;
            size_t gb = (size_t)(nbase + r) * KTOT + kc + kq * 4;
            int so = r * 72 + kq * 4;
            *(uint2*)&sAhi[so] = *(const uint2*)&Ahi[ga];
            *(uint2*)&sAlo[so] = *(const uint2*)&Alo[ga];
            *(uint2*)&sBhi[so] = *(const uint2*)&Bthi[gb];
            *(uint2*)&sBlo[so] = *(const uint2*)&Btlo[gb];
        }
        __syncthreads();

        #pragma unroll
        for (int ks = 0; ks < 4; ks++) {
            int k0 = ks * 16;
            uint32_t ah[2][4], al[2][4];
            #pragma unroll
            for (int mi = 0; mi < 2; mi++) {
                int r0 = wm * 32 + mi * 16 + (lane >> 2);
                int c0 = k0 + (lane & 3) * 2;
                ah[mi][0] = *(uint32_t*)&sAhi[r0 * 72 + c0];
                ah[mi][1] = *(uint32_t*)&sAhi[(r0 + 8) * 72 + c0];
                ah[mi][2] = *(uint32_t*)&sAhi[r0 * 72 + c0 + 8];
                ah[mi][3] = *(uint32_t*)&sAhi[(r0 + 8) * 72 + c0 + 8];
                al[mi][0] = *(uint32_t*)&sAlo[r0 * 72 + c0];
                al[mi][1] = *(uint32_t*)&sAlo[(r0 + 8) * 72 + c0];
                al[mi][2] = *(uint32_t*)&sAlo[r0 * 72 + c0 + 8];
                al[mi][3] = *(uint32_t*)&sAlo[(r0 + 8) * 72 + c0 + 8];
            }
            #pragma unroll
            for (int nj = 0; nj < 8; nj++) {
                int nr = wn * 64 + nj * 8 + (lane >> 2);
                int ck = k0 + (lane & 3) * 2;
                uint32_t bh0 = *(uint32_t*)&sBhi[nr * 72 + ck];
                uint32_t bh1 = *(uint32_t*)&sBhi[nr * 72 + ck + 8];
                uint32_t bl0 = *(uint32_t*)&sBlo[nr * 72 + ck];
                uint32_t bl1 = *(uint32_t*)&sBlo[nr * 72 + ck + 8];
                #pragma unroll
                for (int mi = 0; mi < 2; mi++) {
                    MMA4(acc[mi][nj], ah[mi], bh0, bh1);
                    MMA4(acc[mi][nj], ah[mi], bl0, bl1);
                    MMA4(acc[mi][nj], al[mi], bh0, bh1);
                }
            }
        }
    }

    // epilogue
    #pragma unroll
    for (int mi = 0; mi < 2; mi++) {
        int r0 = mbase + wm * 32 + mi * 16 + (lane >> 2);
        #pragma unroll
        for (int nj = 0; nj < 8; nj++) {
            int col = nbase + wn * 64 + nj * 8 + (lane & 3) * 2;
            if (col < ncols) {
                float2 bb = *(const float2*)&bias[col];
                float v0 = acc[mi][nj][0] + bb.x;
                float v1 = acc[mi][nj][1] + bb.y;
                float v2 = acc[mi][nj][2] + bb.x;
                float v3 = acc[mi][nj][3] + bb.y;
                if (RELU) {
                    v0 = fmaxf(v0, 0.f); v1 = fmaxf(v1, 0.f);
                    v2 = fmaxf(v2, 0.f); v3 = fmaxf(v3, 0.f);
                }
                if (r0 < NN)
                    *(float2*)&out[(size_t)r0 * outStride + col] = make_float2(v0, v1);
                if (r0 + 8 < NN)
                    *(float2*)&out[(size_t)(r0 + 8) * outStride + col] = make_float2(v2, v3);
            }
        }
    }
}

// ---------------- softmax over 1000 classes, one warp per node ----------------
__global__ void k_softmax(float* __restrict__ out) {
    int w = (blockIdx.x * blockDim.x + threadIdx.x) >> 5;
    int lane = threadIdx.x & 31;
    if (w >= NN) return;
    float* row = out + (size_t)w * VC;
    float vals[32];
    float m = -1e30f;
    #pragma unroll
    for (int i = 0; i < 32; i++) {
        int c = lane + i * 32;
        float v = (c < VC) ? row[c] : -1e30f;
        vals[i] = v;
        m = fmaxf(m, v);
    }
    #pragma unroll
    for (int o = 16; o; o >>= 1) m = fmaxf(m, __shfl_xor_sync(0xffffffffu, m, o));
    float s = 0.f;
    #pragma unroll
    for (int i = 0; i < 32; i++) {
        float e = __expf(vals[i] - m);
        vals[i] = e;
        s += e;
    }
    #pragma unroll
    for (int o = 16; o; o >>= 1) s += __shfl_xor_sync(0xffffffffu, s, o);
    float inv = 1.0f / s;
    #pragma unroll
    for (int i = 0; i < 32; i++) {
        int c = lane + i * 32;
        if (c < VC) row[c] = vals[i] * inv;
    }
}

// ---------------- launch ------------------------------------------------------
extern "C" void kernel_launch(void* const* d_in, const int* in_sizes, int n_in,
                              void* d_out, int out_size) {
    const int*   x     = (const int*)d_in[0];
    const int*   ei    = (const int*)d_in[1];
    const int*   src   = ei;
    const int*   dst   = ei + NE;
    const float* emb   = (const float*)d_in[2];
    const float* Wl    = (const float*)d_in[3];
    const float* bl    = (const float*)d_in[4];
    const float* Wr    = (const float*)d_in[5];
    const float* Wlast = (const float*)d_in[6];
    const float* blast = (const float*)d_in[7];
    float* out = (float*)d_out;

    cudaFuncSetAttribute(k_mma_gemm<256, true>,
                         cudaFuncAttributeMaxDynamicSharedMemorySize, GSMEM);
    cudaFuncSetAttribute(k_mma_gemm<128, false>,
                         cudaFuncAttributeMaxDynamicSharedMemorySize, GSMEM);

    float *hA, *hB;
    cudaGetSymbolAddress((void**)&hA, g_hA);
    cudaGetSymbolAddress((void**)&hB, g_hB);
    __nv_bfloat16 *Ahi, *Alo, *FAhi, *FAlo, *BthiL, *BtloL, *BthiF, *BtloF;
    cudaGetSymbolAddress((void**)&Ahi, g_Ahi);
    cudaGetSymbolAddress((void**)&Alo, g_Alo);
    cudaGetSymbolAddress((void**)&FAhi, g_FAhi);
    cudaGetSymbolAddress((void**)&FAlo, g_FAlo);
    cudaGetSymbolAddress((void**)&BthiL, g_BthiL);
    cudaGetSymbolAddress((void**)&BtloL, g_BtloL);
    cudaGetSymbolAddress((void**)&BthiF, g_BthiF);
    cudaGetSymbolAddress((void**)&BtloF, g_BtloF);

    k_zero<<<(NN + 255) / 256, 256>>>();
    k_hist<<<(NE + 255) / 256, 256>>>(dst);
    k_scan1<<<NB_SCAN, 1024>>>();
    k_scan2<<<1, 32>>>();
    k_scan3<<<NB_SCAN, 1024>>>();
    k_scatter<<<(NE + 255) / 256, 256>>>(src, dst);
    k_embed<<<(NN * 32 + 255) / 256, 256>>>(x, emb);
    k_convB_F<<<(1024 * 64 + 255) / 256, 256>>>(Wlast);

    float* hin = hA;
    float* hout = hB;
    for (int l = 0; l < 3; l++) {
        k_agg<<<(NN * 32 + 255) / 256, 256>>>(hin);
        k_convA_L<<<(MROWS * 128 + 255) / 256, 256>>>(hin);
        k_convB_L<<<(128 * 128 + 255) / 256, 256>>>(Wl + l * HD * HD, Wr + l * HD * HD);
        k_mma_gemm<256, true><<<dim3(NT, 1), 256, GSMEM>>>(
            Ahi, Alo, BthiL, BtloL, bl + l * HD, hout, HD, HD);
        float* t = hin; hin = hout; hout = t;
    }

    k_convA_F<<<(MROWS * 64 + 255) / 256, 256>>>(hin);
    k_mma_gemm<128, false><<<dim3(NT, 8), 256, GSMEM>>>(
        FAhi, FAlo, BthiF, BtloF, blast, out, VC, VC);
    k_softmax<<<(NN * 32 + 255) / 256, 256>>>(out);
}